// round 16
// baseline (speedup 1.0000x reference)
#include <cuda_runtime.h>
#include <cuda_bf16.h>
#include <cstdint>

#define BATCH 32
#define SEQ 512
#define RELDIM 1024
#define NH 16
#define HD 64
#define REMB 256
#define SCALE 0.125f
#define LOG2E 1.4426950408889634f

#define K2 (2 * RELDIM)   // 2048: [hi | lo]

// ---------------- scratch (device globals; no allocations allowed) -----------
__device__ float g_sim[SEQ * SEQ];
__device__ __nv_bfloat16 g_A2[(size_t)BATCH * SEQ * K2];
__device__ __nv_bfloat16 g_C2[(size_t)BATCH * SEQ * K2];
__device__ __nv_bfloat16 g_Wqkv2[(size_t)3 * RELDIM * K2];   // stacked Wq|Wk|Wv
__device__ __nv_bfloat16 g_Wo2[(size_t)RELDIM * K2];
// attention operands: [b*16+h][s][hi 64 | lo 64] bf16
__device__ __nv_bfloat16 g_Q2[(size_t)BATCH * NH * SEQ * 128];
__device__ __nv_bfloat16 g_K2[(size_t)BATCH * NH * SEQ * 128];
__device__ __nv_bfloat16 g_V2[(size_t)BATCH * NH * SEQ * 128];

// ======================= PTX helpers (base sm_103 target only) ==============
__device__ __forceinline__ uint32_t smem_u32(const void* p) {
    uint32_t a;
    asm("{ .reg .u64 t; cvta.to.shared.u64 t, %1; cvt.u32.u64 %0, t; }"
        : "=r"(a) : "l"(p));
    return a;
}
__device__ __forceinline__ void cp_async16(uint32_t dst, const void* src) {
    asm volatile("cp.async.cg.shared.global [%0], [%1], 16;\n"
                 :: "r"(dst), "l"(src));
}
__device__ __forceinline__ void cp_commit() {
    asm volatile("cp.async.commit_group;\n" ::: "memory");
}
template <int N>
__device__ __forceinline__ void cp_wait() {
    asm volatile("cp.async.wait_group %0;\n" :: "n"(N) : "memory");
}
__device__ __forceinline__ void ldm_x4(uint32_t& d0, uint32_t& d1, uint32_t& d2,
                                       uint32_t& d3, uint32_t addr) {
    asm volatile("ldmatrix.sync.aligned.m8n8.x4.shared.b16 {%0,%1,%2,%3}, [%4];"
                 : "=r"(d0), "=r"(d1), "=r"(d2), "=r"(d3) : "r"(addr));
}
__device__ __forceinline__ void ldm_x4_t(uint32_t& d0, uint32_t& d1, uint32_t& d2,
                                         uint32_t& d3, uint32_t addr) {
    asm volatile("ldmatrix.sync.aligned.m8n8.x4.trans.shared.b16 {%0,%1,%2,%3}, [%4];"
                 : "=r"(d0), "=r"(d1), "=r"(d2), "=r"(d3) : "r"(addr));
}
__device__ __forceinline__ void mma_bf16(float* c, const uint32_t* a,
                                         uint32_t b0, uint32_t b1) {
    asm volatile(
        "mma.sync.aligned.m16n8k16.row.col.f32.bf16.bf16.f32 "
        "{%0,%1,%2,%3}, {%4,%5,%6,%7}, {%8,%9}, {%0,%1,%2,%3};"
        : "+f"(c[0]), "+f"(c[1]), "+f"(c[2]), "+f"(c[3])
        : "r"(a[0]), "r"(a[1]), "r"(a[2]), "r"(a[3]), "r"(b0), "r"(b1));
}

// =================== split fp32 -> bf16 [hi | lo] (K-concat) ================
__device__ __forceinline__ void split2_body(const float* __restrict__ X,
                                            __nv_bfloat16* __restrict__ Y,
                                            int i, int Kd) {
    int k4 = Kd >> 2;
    int r = i / k4;
    int kq = (i - r * k4) << 2;
    float4 v = ((const float4*)X)[i];
    __nv_bfloat16 h0 = __float2bfloat16(v.x);
    __nv_bfloat16 h1 = __float2bfloat16(v.y);
    __nv_bfloat16 h2 = __float2bfloat16(v.z);
    __nv_bfloat16 h3 = __float2bfloat16(v.w);
    __nv_bfloat16 l0 = __float2bfloat16(v.x - __bfloat162float(h0));
    __nv_bfloat16 l1 = __float2bfloat16(v.y - __bfloat162float(h1));
    __nv_bfloat16 l2 = __float2bfloat16(v.z - __bfloat162float(h2));
    __nv_bfloat16 l3 = __float2bfloat16(v.w - __bfloat162float(h3));
    __nv_bfloat16* row = Y + (size_t)r * (2 * Kd);
    *(__nv_bfloat162*)(row + kq)          = __nv_bfloat162(h0, h1);
    *(__nv_bfloat162*)(row + kq + 2)      = __nv_bfloat162(h2, h3);
    *(__nv_bfloat162*)(row + Kd + kq)     = __nv_bfloat162(l0, l1);
    *(__nv_bfloat162*)(row + Kd + kq + 2) = __nv_bfloat162(l2, l3);
}

// ------- unified split: blocks [0,2048) = 4 weights, [2048,...) = h_R -------
__global__ void __launch_bounds__(256) split_all(
    const float* __restrict__ XA, __nv_bfloat16* __restrict__ YA, int t4,
    const float* __restrict__ W0, const float* __restrict__ W1,
    const float* __restrict__ W2, const float* __restrict__ W3,
    __nv_bfloat16* __restrict__ Y0, __nv_bfloat16* __restrict__ Y1,
    __nv_bfloat16* __restrict__ Y2, __nv_bfloat16* __restrict__ Y3,
    int w4) {
    int bx = blockIdx.x;
    const float* X;
    __nv_bfloat16* Y;
    int base, total;
    if (bx < 2048) {
        switch (bx >> 9) {
            case 0:  X = W0; Y = Y0; break;
            case 1:  X = W1; Y = Y1; break;
            case 2:  X = W2; Y = Y2; break;
            default: X = W3; Y = Y3; break;
        }
        base = (bx & 511) * 512;
        total = w4;
    } else {
        X = XA; Y = YA;
        base = (bx - 2048) * 512;
        total = t4;
    }
    int i = base + threadIdx.x;
    if (i < total) split2_body(X, Y, i, RELDIM);
    int i2 = i + 256;
    if (i2 < total) split2_body(X, Y, i2, RELDIM);
}

// ============ mma.sync bf16 NT GEMM, [hi|lo] fragment-reuse 3-product =======
// Epilogue stages the 128x128 tile in smem (rows padded to 528B) and streams
// out with fully-coalesced 16B stores.
#define GM_STAGE 32768   // A 16KB + B 16KB
#define EP_ROW 528       // 512B data + 16B pad (16B aligned)
__global__ void __launch_bounds__(256, 2) gemm_mma(
    const __nv_bfloat16* __restrict__ A, const __nv_bfloat16* __restrict__ B,
    float* __restrict__ C,
    __nv_bfloat16* __restrict__ Cq, __nv_bfloat16* __restrict__ Ck,
    __nv_bfloat16* __restrict__ Cv,
    int N, int Kd, int outmode) {
    extern __shared__ char sm[];
    const uint32_t smbase = smem_u32(sm);
    const int tid = threadIdx.x;
    const int wid = tid >> 5;
    const int lane = tid & 31;
    const int bm = blockIdx.y * 128;
    const int bn = blockIdx.x * 128;
    const __nv_bfloat16* Ag = A + (size_t)bm * Kd;
    const __nv_bfloat16* Bg = B + (size_t)bn * Kd;
    const int khalf = Kd >> 1;          // 1024
    const int nch = khalf >> 5;         // chunks of 32 original k

    const int u = tid & 7;
    const int koff = (u < 4) ? (u * 8) : (khalf + (u - 4) * 8);
    const uint32_t usw = (uint32_t)(u << 4);

    auto load = [&](int ch, int st) {
        uint32_t abase = smbase + st * GM_STAGE;
        uint32_t bbase = abase + 16384;
        const __nv_bfloat16* ac = Ag + ch * 32 + koff;
        const __nv_bfloat16* bc = Bg + ch * 32 + koff;
        #pragma unroll
        for (int v = 0; v < 4; v++) {
            int r = v * 32 + (tid >> 3);
            uint32_t off = (uint32_t)(r * 128) + ((usw ^ ((uint32_t)(r & 7) << 4)));
            cp_async16(abase + off, ac + (size_t)r * Kd);
            cp_async16(bbase + off, bc + (size_t)r * Kd);
        }
        cp_commit();
    };

    float acc[2][8][4];
    #pragma unroll
    for (int mt = 0; mt < 2; mt++)
        #pragma unroll
        for (int nt = 0; nt < 8; nt++)
            #pragma unroll
            for (int j = 0; j < 4; j++) acc[mt][nt][j] = 0.f;

    const int wm = (wid & 3) * 32;
    const int wn = (wid >> 2) * 64;
    const int g = lane >> 3;
    const int rr = ((g & 1) << 3) + (lane & 7);
    const int kg = g >> 1;
    const int swl = lane & 7;

    load(0, 0);
    load(1, 1);

    for (int ch = 0; ch < nch; ch++) {
        if (ch == nch - 1) cp_wait<0>(); else cp_wait<1>();
        __syncthreads();
        if (ch + 2 < nch) load(ch + 2, (ch + 2) % 3);

        uint32_t abase = smbase + (ch % 3) * GM_STAGE;
        uint32_t bbase = abase + 16384;
        #pragma unroll
        for (int ks = 0; ks < 2; ks++) {
            uint32_t swh = (uint32_t)((((2 * ks + kg) ^ swl) & 7) << 4);
            uint32_t swo = (uint32_t)((((4 + 2 * ks + kg) ^ swl) & 7) << 4);
            uint32_t ah[2][4], al[2][4];
            #pragma unroll
            for (int mt = 0; mt < 2; mt++) {
                int row = wm + mt * 16 + rr;
                ldm_x4(ah[mt][0], ah[mt][1], ah[mt][2], ah[mt][3],
                       abase + (uint32_t)(row * 128) + swh);
                ldm_x4(al[mt][0], al[mt][1], al[mt][2], al[mt][3],
                       abase + (uint32_t)(row * 128) + swo);
            }
            #pragma unroll
            for (int nt2 = 0; nt2 < 4; nt2++) {
                int brow = wn + nt2 * 16 + rr;
                uint32_t bh[4], bl[4];
                ldm_x4(bh[0], bh[1], bh[2], bh[3],
                       bbase + (uint32_t)(brow * 128) + swh);
                #pragma unroll
                for (int mt = 0; mt < 2; mt++)
                    #pragma unroll
                    for (int sub = 0; sub < 2; sub++) {
                        mma_bf16(acc[mt][2 * nt2 + sub], ah[mt], bh[sub], bh[2 + sub]);
                        mma_bf16(acc[mt][2 * nt2 + sub], al[mt], bh[sub], bh[2 + sub]);
                    }
                ldm_x4(bl[0], bl[1], bl[2], bl[3],
                       bbase + (uint32_t)(brow * 128) + swo);
                #pragma unroll
                for (int mt = 0; mt < 2; mt++)
                    #pragma unroll
                    for (int sub = 0; sub < 2; sub++)
                        mma_bf16(acc[mt][2 * nt2 + sub], ah[mt], bl[sub], bl[2 + sub]);
            }
        }
    }

    // ---- staged epilogue: smem (128 x EP_ROW) then coalesced 16B stores ----
    __syncthreads();   // all warps done reading stage buffers
    if (outmode == 0) {
        #pragma unroll
        for (int mt = 0; mt < 2; mt++)
            #pragma unroll
            for (int nt = 0; nt < 8; nt++)
                #pragma unroll
                for (int half = 0; half < 2; half++) {
                    int srow = wm + mt * 16 + half * 8 + (lane >> 2);
                    int scol = wn + (lane & 3) * 2 + nt * 8;
                    *(float2*)(sm + srow * EP_ROW + scol * 4) =
                        make_float2(acc[mt][nt][half * 2 + 0],
                                    acc[mt][nt][half * 2 + 1]);
                }
        __syncthreads();
        #pragma unroll
        for (int it = 0; it < 16; it++) {
            int id = it * 256 + tid;
            int row = id >> 5, ci = id & 31;
            float4 v = *(const float4*)(sm + row * EP_ROW + ci * 16);
            *(float4*)(C + (size_t)(bm + row) * N + bn + ci * 4) = v;
        }
    } else {
        const int tgt = bn >> 10;
        __nv_bfloat16* OUT = (tgt == 0) ? Cq : ((tgt == 1) ? Ck : Cv);
        const int h0 = (bn & 1023) >> 6;          // two heads per CTA tile
        const int b = bm >> 9, s0 = bm & 511;
        #pragma unroll
        for (int mt = 0; mt < 2; mt++)
            #pragma unroll
            for (int nt = 0; nt < 8; nt++)
                #pragma unroll
                for (int half = 0; half < 2; half++) {
                    int srow = wm + mt * 16 + half * 8 + (lane >> 2);
                    int cl = wn + (lane & 3) * 2 + nt * 8;
                    int hh = cl >> 6, d = cl & 63;
                    float x = acc[mt][nt][half * 2 + 0];
                    float y = acc[mt][nt][half * 2 + 1];
                    __nv_bfloat162 h2 = __float22bfloat162_rn(make_float2(x, y));
                    float2 hf = __bfloat1622float2(h2);
                    __nv_bfloat162 l2 = __float22bfloat162_rn(
                        make_float2(x - hf.x, y - hf.y));
                    char* p = sm + srow * EP_ROW + hh * 256 + d * 2;
                    *(__nv_bfloat162*)p = h2;
                    *(__nv_bfloat162*)(p + 128) = l2;
                }
        __syncthreads();
        #pragma unroll
        for (int it = 0; it < 16; it++) {
            int id = it * 256 + tid;
            int row = id >> 5, rem = id & 31;
            int hh = rem >> 4, ci = rem & 15;
            float4 v = *(const float4*)(sm + row * EP_ROW + hh * 256 + ci * 16);
            char* dst = (char*)(OUT +
                (((size_t)(b * 16 + h0 + hh) * 512 + s0 + row) * 128)) + ci * 16;
            *(float4*)dst = v;
        }
    }
}

// ------- sim GEMM with fused normalization: sim = (R R^T)/(|r_i||r_j|) ------
__global__ void __launch_bounds__(128) gemm_sim(const float* __restrict__ R,
                                                float* __restrict__ C) {
    __shared__ float As[16][64];
    __shared__ float Bs[16][64];
    const int tid = threadIdx.x;
    const int bm = blockIdx.y * 64;
    const int bn = blockIdx.x * 64;
    const int tx = tid & 15;
    const int ty = tid >> 4;

    float acc[8][4];
    float ssA[8], ssB[4];
    #pragma unroll
    for (int i = 0; i < 8; i++) {
        ssA[i] = 0.f;
        #pragma unroll
        for (int j = 0; j < 4; j++) acc[i][j] = 0.f;
    }
    #pragma unroll
    for (int j = 0; j < 4; j++) ssB[j] = 0.f;

    for (int kt = 0; kt < REMB; kt += 16) {
        #pragma unroll
        for (int uu = 0; uu < 2; uu++) {
            int f = uu * 128 + tid;
            int row = f >> 2;
            int kc = (f & 3) << 2;
            float4 av = *(const float4*)(R + (size_t)(bm + row) * REMB + kt + kc);
            As[kc + 0][row] = av.x; As[kc + 1][row] = av.y;
            As[kc + 2][row] = av.z; As[kc + 3][row] = av.w;
            float4 bv = *(const float4*)(R + (size_t)(bn + row) * REMB + kt + kc);
            Bs[kc + 0][row] = bv.x; Bs[kc + 1][row] = bv.y;
            Bs[kc + 2][row] = bv.z; Bs[kc + 3][row] = bv.w;
        }
        __syncthreads();
        #pragma unroll
        for (int k = 0; k < 16; k++) {
            float a[8], b[4];
            *(float4*)&a[0] = *(const float4*)&As[k][ty * 8];
            *(float4*)&a[4] = *(const float4*)&As[k][ty * 8 + 4];
            *(float4*)&b[0] = *(const float4*)&Bs[k][tx * 4];
            #pragma unroll
            for (int i = 0; i < 8; i++) {
                ssA[i] = fmaf(a[i], a[i], ssA[i]);
                #pragma unroll
                for (int j = 0; j < 4; j++)
                    acc[i][j] = fmaf(a[i], b[j], acc[i][j]);
            }
            #pragma unroll
            for (int j = 0; j < 4; j++) ssB[j] = fmaf(b[j], b[j], ssB[j]);
        }
        __syncthreads();
    }
    float invc[4];
    #pragma unroll
    for (int j = 0; j < 4; j++)
        invc[j] = 1.f / fmaxf(sqrtf(ssB[j]), 1e-12f);
    #pragma unroll
    for (int i = 0; i < 8; i++) {
        float invr = 1.f / fmaxf(sqrtf(ssA[i]), 1e-12f);
        *(float4*)(C + (size_t)(bm + ty * 8 + i) * SEQ + bn + tx * 4) =
            make_float4(acc[i][0] * invr * invc[0], acc[i][1] * invr * invc[1],
                        acc[i][2] * invr * invc[2], acc[i][3] * invr * invc[3]);
    }
}

// ---------------- tensor-core flash attention with sim bias -----------------
// grid (4, 512): x = q-tile (128), y = b*16+h. 8 warps, warp = 16 q rows.
// log2-domain softmax; PV full 3-product; staged coalesced ctx epilogue.
#define FA_SK 32768
#define FA_SV 65536
#define FA_SMEM 98304
#define FE_ROW 272   // 256B data (hi128|lo128) + 16B pad
__global__ void __launch_bounds__(256, 2) flash_mma(
    const __nv_bfloat16* __restrict__ Q2, const __nv_bfloat16* __restrict__ K2g,
    const __nv_bfloat16* __restrict__ V2, const float* __restrict__ sim,
    const float* __restrict__ wsim, __nv_bfloat16* __restrict__ C2) {
    extern __shared__ char sm[];
    const uint32_t sb = smem_u32(sm);
    const int tid = threadIdx.x;
    const int wid = tid >> 5;
    const int lane = tid & 31;
    const int bh = blockIdx.y;
    const int b = bh >> 4, h = bh & 15;
    const int q0 = blockIdx.x * 128;
    const __nv_bfloat16* Qg = Q2 + ((size_t)bh * 512 + q0) * 128;
    const __nv_bfloat16* Kg = K2g + (size_t)bh * 512 * 128;
    const __nv_bfloat16* Vg = V2 + (size_t)bh * 512 * 128;
    const float wh = wsim[h] * LOG2E;
    const float SC2 = SCALE * LOG2E;
    const float NEG_INF = __int_as_float(0xff800000u);

    #pragma unroll
    for (int u = 0; u < 8; u++) {
        int idx = u * 256 + tid;
        int r = idx >> 4, un = idx & 15;
        uint32_t soff = (uint32_t)(r * 256) + (uint32_t)((un >> 3) * 128) +
                        (uint32_t)((((un & 7) ^ (r & 7)) & 7) << 4);
        cp_async16(sb + soff, Qg + (size_t)r * 128 + un * 8);
    }
    cp_commit();

    auto load_kv = [&](int kt, int st) {
        const __nv_bfloat16* kc = Kg + (size_t)kt * 64 * 128;
        const __nv_bfloat16* vc = Vg + (size_t)kt * 64 * 128;
        uint32_t kb = sb + FA_SK + st * 16384;
        uint32_t vb = sb + FA_SV + st * 16384;
        #pragma unroll
        for (int u = 0; u < 4; u++) {
            int idx = u * 256 + tid;
            int r = idx >> 4, un = idx & 15;
            uint32_t soff = (uint32_t)(r * 256) + (uint32_t)((un >> 3) * 128) +
                            (uint32_t)((((un & 7) ^ (r & 7)) & 7) << 4);
            cp_async16(kb + soff, kc + (size_t)r * 128 + un * 8);
            cp_async16(vb + soff, vc + (size_t)r * 128 + un * 8);
        }
        cp_commit();
    };
    load_kv(0, 0);
    load_kv(1, 1);

    float O[8][4];
    #pragma unroll
    for (int j = 0; j < 8; j++)
        #pragma unroll
        for (int t = 0; t < 4; t++) O[j][t] = 0.f;
    float m0 = NEG_INF, m1 = NEG_INF, l0 = 0.f, l1 = 0.f;

    const int lrow = lane & 15;
    const int lsel = lane >> 4;
    const int qg0 = q0 + wid * 16 + (lane >> 2);
    const int qr = wid * 16 + lrow;

    for (int kt = 0; kt < 8; kt++) {
        if (kt == 7) cp_wait<0>(); else cp_wait<1>();
        __syncthreads();
        uint32_t kbase = sb + FA_SK + (kt & 1) * 16384;
        uint32_t vbase = sb + FA_SV + (kt & 1) * 16384;

        float S[8][4];
        #pragma unroll
        for (int j = 0; j < 8; j++)
            #pragma unroll
            for (int t = 0; t < 4; t++) S[j][t] = 0.f;

        #pragma unroll
        for (int c = 0; c < 4; c++) {
            uint32_t qco = (uint32_t)((((2 * c + lsel) ^ (qr & 7)) & 7) << 4);
            uint32_t aqh[4], aql[4];
            ldm_x4(aqh[0], aqh[1], aqh[2], aqh[3], sb + (uint32_t)(qr * 256) + qco);
            ldm_x4(aql[0], aql[1], aql[2], aql[3],
                   sb + (uint32_t)(qr * 256) + 128 + qco);
            #pragma unroll
            for (int kg = 0; kg < 4; kg++) {
                int kr = kg * 16 + lrow;
                uint32_t kco = (uint32_t)((((2 * c + lsel) ^ (kr & 7)) & 7) << 4);
                uint32_t bkh[4], bkl[4];
                ldm_x4(bkh[0], bkh[1], bkh[2], bkh[3],
                       kbase + (uint32_t)(kr * 256) + kco);
                ldm_x4(bkl[0], bkl[1], bkl[2], bkl[3],
                       kbase + (uint32_t)(kr * 256) + 128 + kco);
                #pragma unroll
                for (int sbt = 0; sbt < 2; sbt++) {
                    int j = 2 * kg + sbt;
                    mma_bf16(S[j], aqh, bkh[sbt], bkh[2 + sbt]);
                    mma_bf16(S[j], aqh, bkl[sbt], bkl[2 + sbt]);
                    mma_bf16(S[j], aql, bkh[sbt], bkh[2 + sbt]);
                }
            }
        }

        const int k0 = kt * 64;
        float mloc0 = NEG_INF, mloc1 = NEG_INF;
        #pragma unroll
        for (int j = 0; j < 8; j++) {
            int key = k0 + 8 * j + (lane & 3) * 2;
            float2 bi0 = *(const float2*)(sim + (size_t)qg0 * SEQ + key);
            float2 bi1 = *(const float2*)(sim + (size_t)(qg0 + 8) * SEQ + key);
            S[j][0] = S[j][0] * SC2 + wh * bi0.x;
            S[j][1] = S[j][1] * SC2 + wh * bi0.y;
            S[j][2] = S[j][2] * SC2 + wh * bi1.x;
            S[j][3] = S[j][3] * SC2 + wh * bi1.y;
            mloc0 = fmaxf(mloc0, fmaxf(S[j][0], S[j][1]));
            mloc1 = fmaxf(mloc1, fmaxf(S[j][2], S[j][3]));
        }
        #pragma unroll
        for (int off = 1; off <= 2; off <<= 1) {
            mloc0 = fmaxf(mloc0, __shfl_xor_sync(0xffffffffu, mloc0, off));
            mloc1 = fmaxf(mloc1, __shfl_xor_sync(0xffffffffu, mloc1, off));
        }
        float mn0 = fmaxf(m0, mloc0), mn1 = fmaxf(m1, mloc1);
        float corr0 = exp2f(m0 - mn0), corr1 = exp2f(m1 - mn1);
        m0 = mn0; m1 = mn1;
        float ps0 = 0.f, ps1 = 0.f;
        #pragma unroll
        for (int j = 0; j < 8; j++) {
            S[j][0] = exp2f(S[j][0] - mn0);
            S[j][1] = exp2f(S[j][1] - mn0);
            S[j][2] = exp2f(S[j][2] - mn1);
            S[j][3] = exp2f(S[j][3] - mn1);
            ps0 += S[j][0] + S[j][1];
            ps1 += S[j][2] + S[j][3];
        }
        #pragma unroll
        for (int off = 1; off <= 2; off <<= 1) {
            ps0 += __shfl_xor_sync(0xffffffffu, ps0, off);
            ps1 += __shfl_xor_sync(0xffffffffu, ps1, off);
        }
        l0 = l0 * corr0 + ps0;
        l1 = l1 * corr1 + ps1;
        #pragma unroll
        for (int j = 0; j < 8; j++) {
            O[j][0] *= corr0; O[j][1] *= corr0;
            O[j][2] *= corr1; O[j][3] *= corr1;
        }

        // ---- O += P V: full 3-product (P hi/lo, V hi/lo) ----
        #pragma unroll
        for (int kg = 0; kg < 4; kg++) {
            uint32_t ph[4], pl[4];
            #pragma unroll
            for (int half = 0; half < 2; half++) {
                #pragma unroll
                for (int rw = 0; rw < 2; rw++) {
                    float x = S[2 * kg + half][rw * 2 + 0];
                    float y = S[2 * kg + half][rw * 2 + 1];
                    __nv_bfloat162 h2 = __float22bfloat162_rn(make_float2(x, y));
                    float2 hf = __bfloat1622float2(h2);
                    __nv_bfloat162 l2 = __float22bfloat162_rn(
                        make_float2(x - hf.x, y - hf.y));
                    ph[half * 2 + rw] = *(uint32_t*)&h2;
                    pl[half * 2 + rw] = *(uint32_t*)&l2;
                }
            }
            int kr = kg * 16 + (lane & 7) + (((lane >> 3) & 1) << 3);
            #pragma unroll
            for (int db = 0; db < 4; db++) {
                uint32_t vco =
                    (uint32_t)((((2 * db + (lane >> 4)) ^ (kr & 7)) & 7) << 4);
                uint32_t vh[4], vl[4];
                ldm_x4_t(vh[0], vh[1], vh[2], vh[3],
                         vbase + (uint32_t)(kr * 256) + vco);
                ldm_x4_t(vl[0], vl[1], vl[2], vl[3],
                         vbase + (uint32_t)(kr * 256) + 128 + vco);
                mma_bf16(O[2 * db], ph, vh[0], vh[1]);
                mma_bf16(O[2 * db], ph, vl[0], vl[1]);
                mma_bf16(O[2 * db], pl, vh[0], vh[1]);
                mma_bf16(O[2 * db + 1], ph, vh[2], vh[3]);
                mma_bf16(O[2 * db + 1], ph, vl[2], vl[3]);
                mma_bf16(O[2 * db + 1], pl, vh[2], vh[3]);
            }
        }
        __syncthreads();
        if (kt + 2 < 8) load_kv(kt + 2, kt & 1);
    }

    // ---- staged epilogue: normalize, split hi/lo into smem, coalesce out ---
    __syncthreads();   // K/V stage buffers dead
    float inv0 = 1.f / l0, inv1 = 1.f / l1;
    #pragma unroll
    for (int j = 0; j < 8; j++) {
        int d = 8 * j + (lane & 3) * 2;
        #pragma unroll
        for (int half = 0; half < 2; half++) {
            int rl = wid * 16 + (lane >> 2) + half * 8;
            float x = O[j][half * 2 + 0] * (half ? inv1 : inv0);
            float y = O[j][half * 2 + 1] * (half ? inv1 : inv0);
            __nv_bfloat162 h2 = __float22bfloat162_rn(make_float2(x, y));
            float2 hf = __bfloat1622float2(h2);
            __nv_bfloat162 l2 = __float22bfloat162_rn(
                make_float2(x - hf.x, y - hf.y));
            char* p = sm + rl * FE_ROW + d * 2;
            *(__nv_bfloat162*)p = h2;
            *(__nv_bfloat162*)(p + 128) = l2;
        }
    }
    __syncthreads();
    const size_t rowbase = (size_t)b * 512 + q0;
    #pragma unroll
    for (int it = 0; it < 8; it++) {
        int id = it * 256 + tid;
        int row = id >> 4, ci = id & 15;
        float4 v = *(const float4*)(sm + row * FE_ROW + ci * 16);
        __nv_bfloat16* dst = C2 + (rowbase + row) * K2 + h * 64 +
                             (ci < 8 ? ci * 8 : RELDIM + (ci - 8) * 8);
        *(float4*)dst = v;
    }
}

// ---------------- launch ----------------------------------------------------
extern "C" void kernel_launch(void* const* d_in, const int* in_sizes, int n_in,
                              void* d_out, int out_size) {
    (void)in_sizes; (void)n_in; (void)out_size;
    const float* h_R  = (const float*)d_in[0];
    const float* R    = (const float*)d_in[1];
    const float* W_q  = (const float*)d_in[2];
    const float* W_k  = (const float*)d_in[3];
    const float* W_v  = (const float*)d_in[4];
    const float* W_o  = (const float*)d_in[5];
    const float* wsim = (const float*)d_in[6];
    float* out = (float*)d_out;

    float *Simp;
    __nv_bfloat16 *A2p, *C2p, *Wqkv2p, *Wo2p, *Q2p, *K2p, *V2p;
    cudaGetSymbolAddress((void**)&Simp,   g_sim);
    cudaGetSymbolAddress((void**)&A2p,    g_A2);
    cudaGetSymbolAddress((void**)&C2p,    g_C2);
    cudaGetSymbolAddress((void**)&Wqkv2p, g_Wqkv2);
    cudaGetSymbolAddress((void**)&Wo2p,   g_Wo2);
    cudaGetSymbolAddress((void**)&Q2p,    g_Q2);
    cudaGetSymbolAddress((void**)&K2p,    g_K2);
    cudaGetSymbolAddress((void**)&V2p,    g_V2);

    const int M = BATCH * SEQ;  // 16384
    const size_t WSZ = (size_t)RELDIM * K2;

    {
        int t4 = M * RELDIM / 4;      // 4194304 -> 8192 blocks
        int w4 = RELDIM * RELDIM / 4; // 262144  -> 512 blocks per weight
        int nblk = 2048 + (t4 + 511) / 512;
        split_all<<<nblk, 256>>>(h_R, A2p, t4,
                                 W_q, W_k, W_v, W_o,
                                 Wqkv2p, Wqkv2p + WSZ, Wqkv2p + 2 * WSZ, Wo2p,
                                 w4);
    }

    constexpr int GEMM_SMEM = 3 * GM_STAGE;  // 98304 >= 128*528
    cudaFuncSetAttribute(gemm_mma, cudaFuncAttributeMaxDynamicSharedMemorySize,
                         GEMM_SMEM);
    gemm_mma<<<dim3(24, M / 128), 256, GEMM_SMEM>>>(
        A2p, Wqkv2p, nullptr, Q2p, K2p, V2p, 3 * RELDIM, K2, 1);

    gemm_sim<<<dim3(SEQ / 64, SEQ / 64), 128>>>(R, Simp);

    cudaFuncSetAttribute(flash_mma, cudaFuncAttributeMaxDynamicSharedMemorySize,
                         FA_SMEM);
    flash_mma<<<dim3(SEQ / 128, BATCH * NH), 256, FA_SMEM>>>(
        Q2p, K2p, V2p, Simp, wsim, C2p);

    gemm_mma<<<dim3(8, M / 128), 256, GEMM_SMEM>>>(
        C2p, Wo2p, out, nullptr, nullptr, nullptr, RELDIM, K2, 0);
}

// round 17
// speedup vs baseline: 1.0043x; 1.0043x over previous
#include <cuda_runtime.h>
#include <cuda_bf16.h>
#include <cstdint>

#define BATCH 32
#define SEQ 512
#define RELDIM 1024
#define NH 16
#define HD 64
#define REMB 256
#define SCALE 0.125f
#define LOG2E 1.4426950408889634f

#define K2 (2 * RELDIM)   // 2048: [hi | lo]

// ---------------- scratch (device globals; no allocations allowed) -----------
__device__ float g_Rn[SEQ * REMB];
__device__ float g_sim[SEQ * SEQ];
__device__ __nv_bfloat16 g_A2[(size_t)BATCH * SEQ * K2];
__device__ __nv_bfloat16 g_C2[(size_t)BATCH * SEQ * K2];
__device__ __nv_bfloat16 g_Wqkv2[(size_t)3 * RELDIM * K2];   // stacked Wq|Wk|Wv
__device__ __nv_bfloat16 g_Wo2[(size_t)RELDIM * K2];
// attention operands: [b*16+h][s][hi 64 | lo 64] bf16
__device__ __nv_bfloat16 g_Q2[(size_t)BATCH * NH * SEQ * 128];
__device__ __nv_bfloat16 g_K2[(size_t)BATCH * NH * SEQ * 128];
__device__ __nv_bfloat16 g_V2[(size_t)BATCH * NH * SEQ * 128];

// ======================= PTX helpers (base sm_103 target only) ==============
__device__ __forceinline__ uint32_t smem_u32(const void* p) {
    uint32_t a;
    asm("{ .reg .u64 t; cvta.to.shared.u64 t, %1; cvt.u32.u64 %0, t; }"
        : "=r"(a) : "l"(p));
    return a;
}
__device__ __forceinline__ void cp_async16(uint32_t dst, const void* src) {
    asm volatile("cp.async.cg.shared.global [%0], [%1], 16;\n"
                 :: "r"(dst), "l"(src));
}
__device__ __forceinline__ void cp_commit() {
    asm volatile("cp.async.commit_group;\n" ::: "memory");
}
template <int N>
__device__ __forceinline__ void cp_wait() {
    asm volatile("cp.async.wait_group %0;\n" :: "n"(N) : "memory");
}
__device__ __forceinline__ void ldm_x4(uint32_t& d0, uint32_t& d1, uint32_t& d2,
                                       uint32_t& d3, uint32_t addr) {
    asm volatile("ldmatrix.sync.aligned.m8n8.x4.shared.b16 {%0,%1,%2,%3}, [%4];"
                 : "=r"(d0), "=r"(d1), "=r"(d2), "=r"(d3) : "r"(addr));
}
__device__ __forceinline__ void ldm_x4_t(uint32_t& d0, uint32_t& d1, uint32_t& d2,
                                         uint32_t& d3, uint32_t addr) {
    asm volatile("ldmatrix.sync.aligned.m8n8.x4.trans.shared.b16 {%0,%1,%2,%3}, [%4];"
                 : "=r"(d0), "=r"(d1), "=r"(d2), "=r"(d3) : "r"(addr));
}
__device__ __forceinline__ void mma_bf16(float* c, const uint32_t* a,
                                         uint32_t b0, uint32_t b1) {
    asm volatile(
        "mma.sync.aligned.m16n8k16.row.col.f32.bf16.bf16.f32 "
        "{%0,%1,%2,%3}, {%4,%5,%6,%7}, {%8,%9}, {%0,%1,%2,%3};"
        : "+f"(c[0]), "+f"(c[1]), "+f"(c[2]), "+f"(c[3])
        : "r"(a[0]), "r"(a[1]), "r"(a[2]), "r"(a[3]), "r"(b0), "r"(b1));
}

// =================== split fp32 -> bf16 [hi | lo] (K-concat) ================
__device__ __forceinline__ void split2_body(const float* __restrict__ X,
                                            __nv_bfloat16* __restrict__ Y,
                                            int i, int Kd) {
    int k4 = Kd >> 2;
    int r = i / k4;
    int kq = (i - r * k4) << 2;
    float4 v = ((const float4*)X)[i];
    __nv_bfloat16 h0 = __float2bfloat16(v.x);
    __nv_bfloat16 h1 = __float2bfloat16(v.y);
    __nv_bfloat16 h2 = __float2bfloat16(v.z);
    __nv_bfloat16 h3 = __float2bfloat16(v.w);
    __nv_bfloat16 l0 = __float2bfloat16(v.x - __bfloat162float(h0));
    __nv_bfloat16 l1 = __float2bfloat16(v.y - __bfloat162float(h1));
    __nv_bfloat16 l2 = __float2bfloat16(v.z - __bfloat162float(h2));
    __nv_bfloat16 l3 = __float2bfloat16(v.w - __bfloat162float(h3));
    __nv_bfloat16* row = Y + (size_t)r * (2 * Kd);
    *(__nv_bfloat162*)(row + kq)          = __nv_bfloat162(h0, h1);
    *(__nv_bfloat162*)(row + kq + 2)      = __nv_bfloat162(h2, h3);
    *(__nv_bfloat162*)(row + Kd + kq)     = __nv_bfloat162(l0, l1);
    *(__nv_bfloat162*)(row + Kd + kq + 2) = __nv_bfloat162(l2, l3);
}

// two independent float4 per thread (MLP=2)
__global__ void __launch_bounds__(256) split2(const float* __restrict__ X,
                                              __nv_bfloat16* __restrict__ Y,
                                              int total4, int Kd) {
    int i = blockIdx.x * 512 + threadIdx.x;
    if (i < total4) split2_body(X, Y, i, Kd);
    int i2 = i + 256;
    if (i2 < total4) split2_body(X, Y, i2, Kd);
}

// fused 4-way weight split: blockIdx.y selects tensor; 2 float4 per thread
__global__ void __launch_bounds__(256) split2w(
    const float* __restrict__ W0, const float* __restrict__ W1,
    const float* __restrict__ W2, const float* __restrict__ W3,
    __nv_bfloat16* __restrict__ Y0, __nv_bfloat16* __restrict__ Y1,
    __nv_bfloat16* __restrict__ Y2, __nv_bfloat16* __restrict__ Y3,
    int total4, int Kd) {
    const float* X;
    __nv_bfloat16* Y;
    switch (blockIdx.y) {
        case 0:  X = W0; Y = Y0; break;
        case 1:  X = W1; Y = Y1; break;
        case 2:  X = W2; Y = Y2; break;
        default: X = W3; Y = Y3; break;
    }
    int i = blockIdx.x * 512 + threadIdx.x;
    if (i < total4) split2_body(X, Y, i, Kd);
    int i2 = i + 256;
    if (i2 < total4) split2_body(X, Y, i2, Kd);
}

// ============ mma.sync bf16 NT GEMM, [hi|lo] fragment-reuse 3-product =======
// Epilogue stages the 128x128 tile in smem (rows padded to 528B) and streams
// out with fully-coalesced 16B stores.
#define GM_STAGE 32768   // A 16KB + B 16KB
#define EP_ROW 528       // 512B data + 16B pad (16B aligned)
__global__ void __launch_bounds__(256, 2) gemm_mma(
    const __nv_bfloat16* __restrict__ A, const __nv_bfloat16* __restrict__ B,
    float* __restrict__ C,
    __nv_bfloat16* __restrict__ Cq, __nv_bfloat16* __restrict__ Ck,
    __nv_bfloat16* __restrict__ Cv,
    int N, int Kd, int outmode) {
    extern __shared__ char sm[];
    const uint32_t smbase = smem_u32(sm);
    const int tid = threadIdx.x;
    const int wid = tid >> 5;
    const int lane = tid & 31;
    const int bm = blockIdx.y * 128;
    const int bn = blockIdx.x * 128;
    const __nv_bfloat16* Ag = A + (size_t)bm * Kd;
    const __nv_bfloat16* Bg = B + (size_t)bn * Kd;
    const int khalf = Kd >> 1;          // 1024
    const int nch = khalf >> 5;         // chunks of 32 original k

    const int u = tid & 7;
    const int koff = (u < 4) ? (u * 8) : (khalf + (u - 4) * 8);
    const uint32_t usw = (uint32_t)(u << 4);

    auto load = [&](int ch, int st) {
        uint32_t abase = smbase + st * GM_STAGE;
        uint32_t bbase = abase + 16384;
        const __nv_bfloat16* ac = Ag + ch * 32 + koff;
        const __nv_bfloat16* bc = Bg + ch * 32 + koff;
        #pragma unroll
        for (int v = 0; v < 4; v++) {
            int r = v * 32 + (tid >> 3);
            uint32_t off = (uint32_t)(r * 128) + ((usw ^ ((uint32_t)(r & 7) << 4)));
            cp_async16(abase + off, ac + (size_t)r * Kd);
            cp_async16(bbase + off, bc + (size_t)r * Kd);
        }
        cp_commit();
    };

    float acc[2][8][4];
    #pragma unroll
    for (int mt = 0; mt < 2; mt++)
        #pragma unroll
        for (int nt = 0; nt < 8; nt++)
            #pragma unroll
            for (int j = 0; j < 4; j++) acc[mt][nt][j] = 0.f;

    const int wm = (wid & 3) * 32;
    const int wn = (wid >> 2) * 64;
    const int g = lane >> 3;
    const int rr = ((g & 1) << 3) + (lane & 7);
    const int kg = g >> 1;
    const int swl = lane & 7;

    load(0, 0);
    load(1, 1);

    for (int ch = 0; ch < nch; ch++) {
        if (ch == nch - 1) cp_wait<0>(); else cp_wait<1>();
        __syncthreads();
        if (ch + 2 < nch) load(ch + 2, (ch + 2) % 3);

        uint32_t abase = smbase + (ch % 3) * GM_STAGE;
        uint32_t bbase = abase + 16384;
        #pragma unroll
        for (int ks = 0; ks < 2; ks++) {
            uint32_t swh = (uint32_t)((((2 * ks + kg) ^ swl) & 7) << 4);
            uint32_t swo = (uint32_t)((((4 + 2 * ks + kg) ^ swl) & 7) << 4);
            uint32_t ah[2][4], al[2][4];
            #pragma unroll
            for (int mt = 0; mt < 2; mt++) {
                int row = wm + mt * 16 + rr;
                ldm_x4(ah[mt][0], ah[mt][1], ah[mt][2], ah[mt][3],
                       abase + (uint32_t)(row * 128) + swh);
                ldm_x4(al[mt][0], al[mt][1], al[mt][2], al[mt][3],
                       abase + (uint32_t)(row * 128) + swo);
            }
            #pragma unroll
            for (int nt2 = 0; nt2 < 4; nt2++) {
                int brow = wn + nt2 * 16 + rr;
                uint32_t bh[4], bl[4];
                ldm_x4(bh[0], bh[1], bh[2], bh[3],
                       bbase + (uint32_t)(brow * 128) + swh);
                #pragma unroll
                for (int mt = 0; mt < 2; mt++)
                    #pragma unroll
                    for (int sub = 0; sub < 2; sub++) {
                        mma_bf16(acc[mt][2 * nt2 + sub], ah[mt], bh[sub], bh[2 + sub]);
                        mma_bf16(acc[mt][2 * nt2 + sub], al[mt], bh[sub], bh[2 + sub]);
                    }
                ldm_x4(bl[0], bl[1], bl[2], bl[3],
                       bbase + (uint32_t)(brow * 128) + swo);
                #pragma unroll
                for (int mt = 0; mt < 2; mt++)
                    #pragma unroll
                    for (int sub = 0; sub < 2; sub++)
                        mma_bf16(acc[mt][2 * nt2 + sub], ah[mt], bl[sub], bl[2 + sub]);
            }
        }
    }

    // ---- staged epilogue: smem (128 x EP_ROW) then coalesced 16B stores ----
    __syncthreads();   // all warps done reading stage buffers
    if (outmode == 0) {
        #pragma unroll
        for (int mt = 0; mt < 2; mt++)
            #pragma unroll
            for (int nt = 0; nt < 8; nt++)
                #pragma unroll
                for (int half = 0; half < 2; half++) {
                    int srow = wm + mt * 16 + half * 8 + (lane >> 2);
                    int scol = wn + (lane & 3) * 2 + nt * 8;
                    *(float2*)(sm + srow * EP_ROW + scol * 4) =
                        make_float2(acc[mt][nt][half * 2 + 0],
                                    acc[mt][nt][half * 2 + 1]);
                }
        __syncthreads();
        #pragma unroll
        for (int it = 0; it < 16; it++) {
            int id = it * 256 + tid;
            int row = id >> 5, ci = id & 31;
            float4 v = *(const float4*)(sm + row * EP_ROW + ci * 16);
            *(float4*)(C + (size_t)(bm + row) * N + bn + ci * 4) = v;
        }
    } else {
        const int tgt = bn >> 10;
        __nv_bfloat16* OUT = (tgt == 0) ? Cq : ((tgt == 1) ? Ck : Cv);
        const int h0 = (bn & 1023) >> 6;          // two heads per CTA tile
        const int b = bm >> 9, s0 = bm & 511;
        #pragma unroll
        for (int mt = 0; mt < 2; mt++)
            #pragma unroll
            for (int nt = 0; nt < 8; nt++)
                #pragma unroll
                for (int half = 0; half < 2; half++) {
                    int srow = wm + mt * 16 + half * 8 + (lane >> 2);
                    int cl = wn + (lane & 3) * 2 + nt * 8;
                    int hh = cl >> 6, d = cl & 63;
                    float x = acc[mt][nt][half * 2 + 0];
                    float y = acc[mt][nt][half * 2 + 1];
                    __nv_bfloat162 h2 = __float22bfloat162_rn(make_float2(x, y));
                    float2 hf = __bfloat1622float2(h2);
                    __nv_bfloat162 l2 = __float22bfloat162_rn(
                        make_float2(x - hf.x, y - hf.y));
                    char* p = sm + srow * EP_ROW + hh * 256 + d * 2;
                    *(__nv_bfloat162*)p = h2;
                    *(__nv_bfloat162*)(p + 128) = l2;
                }
        __syncthreads();
        #pragma unroll
        for (int it = 0; it < 16; it++) {
            int id = it * 256 + tid;
            int row = id >> 5, rem = id & 31;
            int hh = rem >> 4, ci = rem & 15;
            float4 v = *(const float4*)(sm + row * EP_ROW + hh * 256 + ci * 16);
            char* dst = (char*)(OUT +
                (((size_t)(b * 16 + h0 + hh) * 512 + s0 + row) * 128)) + ci * 16;
            *(float4*)dst = v;
        }
    }
}

// ---------------- row-normalize R ------------------------------------------
__global__ void __launch_bounds__(256) norm_kernel(const float* __restrict__ R,
                                                   float* __restrict__ Rn) {
    int r = blockIdx.x;
    int t = threadIdx.x;
    float v = R[r * REMB + t];
    float s = v * v;
    #pragma unroll
    for (int off = 16; off > 0; off >>= 1)
        s += __shfl_xor_sync(0xffffffffu, s, off);
    __shared__ float red[8];
    __shared__ float invn;
    if ((t & 31) == 0) red[t >> 5] = s;
    __syncthreads();
    if (t == 0) {
        float tot = 0.f;
        #pragma unroll
        for (int i = 0; i < 8; i++) tot += red[i];
        invn = 1.f / fmaxf(sqrtf(tot), 1e-12f);
    }
    __syncthreads();
    Rn[r * REMB + t] = v * invn;
}

// ---------------- small fp32 NT GEMM (sim matrix only), 64x64 tiles ---------
__global__ void __launch_bounds__(128) gemm_nt64(const float* __restrict__ A,
                                                 const float* __restrict__ B,
                                                 float* __restrict__ C,
                                                 int M, int N, int Kd) {
    __shared__ float As[16][64];
    __shared__ float Bs[16][64];
    const int tid = threadIdx.x;
    const int bm = blockIdx.y * 64;
    const int bn = blockIdx.x * 64;
    const int tx = tid & 15;
    const int ty = tid >> 4;

    float acc[8][4];
    #pragma unroll
    for (int i = 0; i < 8; i++)
        #pragma unroll
        for (int j = 0; j < 4; j++) acc[i][j] = 0.f;

    for (int kt = 0; kt < Kd; kt += 16) {
        #pragma unroll
        for (int uu = 0; uu < 2; uu++) {
            int f = uu * 128 + tid;
            int row = f >> 2;
            int kc = (f & 3) << 2;
            float4 av = *(const float4*)(A + (size_t)(bm + row) * Kd + kt + kc);
            As[kc + 0][row] = av.x; As[kc + 1][row] = av.y;
            As[kc + 2][row] = av.z; As[kc + 3][row] = av.w;
            float4 bv = *(const float4*)(B + (size_t)(bn + row) * Kd + kt + kc);
            Bs[kc + 0][row] = bv.x; Bs[kc + 1][row] = bv.y;
            Bs[kc + 2][row] = bv.z; Bs[kc + 3][row] = bv.w;
        }
        __syncthreads();
        #pragma unroll
        for (int k = 0; k < 16; k++) {
            float a[8], b[4];
            *(float4*)&a[0] = *(const float4*)&As[k][ty * 8];
            *(float4*)&a[4] = *(const float4*)&As[k][ty * 8 + 4];
            *(float4*)&b[0] = *(const float4*)&Bs[k][tx * 4];
            #pragma unroll
            for (int i = 0; i < 8; i++)
                #pragma unroll
                for (int j = 0; j < 4; j++)
                    acc[i][j] = fmaf(a[i], b[j], acc[i][j]);
        }
        __syncthreads();
    }
    #pragma unroll
    for (int i = 0; i < 8; i++)
        *(float4*)(C + (size_t)(bm + ty * 8 + i) * N + bn + tx * 4) =
            make_float4(acc[i][0], acc[i][1], acc[i][2], acc[i][3]);
}

// ---------------- tensor-core flash attention with sim bias -----------------
// grid (4, 512): x = q-tile (128), y = b*16+h. 8 warps, warp = 16 q rows.
// log2-domain softmax; PV full 3-product; staged coalesced ctx epilogue.
#define FA_SK 32768
#define FA_SV 65536
#define FA_SMEM 98304
#define FE_ROW 272   // 256B data (hi128|lo128) + 16B pad
__global__ void __launch_bounds__(256, 2) flash_mma(
    const __nv_bfloat16* __restrict__ Q2, const __nv_bfloat16* __restrict__ K2g,
    const __nv_bfloat16* __restrict__ V2, const float* __restrict__ sim,
    const float* __restrict__ wsim, __nv_bfloat16* __restrict__ C2) {
    extern __shared__ char sm[];
    const uint32_t sb = smem_u32(sm);
    const int tid = threadIdx.x;
    const int wid = tid >> 5;
    const int lane = tid & 31;
    const int bh = blockIdx.y;
    const int b = bh >> 4, h = bh & 15;
    const int q0 = blockIdx.x * 128;
    const __nv_bfloat16* Qg = Q2 + ((size_t)bh * 512 + q0) * 128;
    const __nv_bfloat16* Kg = K2g + (size_t)bh * 512 * 128;
    const __nv_bfloat16* Vg = V2 + (size_t)bh * 512 * 128;
    const float wh = wsim[h] * LOG2E;
    const float SC2 = SCALE * LOG2E;
    const float NEG_INF = __int_as_float(0xff800000u);

    #pragma unroll
    for (int u = 0; u < 8; u++) {
        int idx = u * 256 + tid;
        int r = idx >> 4, un = idx & 15;
        uint32_t soff = (uint32_t)(r * 256) + (uint32_t)((un >> 3) * 128) +
                        (uint32_t)((((un & 7) ^ (r & 7)) & 7) << 4);
        cp_async16(sb + soff, Qg + (size_t)r * 128 + un * 8);
    }
    cp_commit();

    auto load_kv = [&](int kt, int st) {
        const __nv_bfloat16* kc = Kg + (size_t)kt * 64 * 128;
        const __nv_bfloat16* vc = Vg + (size_t)kt * 64 * 128;
        uint32_t kb = sb + FA_SK + st * 16384;
        uint32_t vb = sb + FA_SV + st * 16384;
        #pragma unroll
        for (int u = 0; u < 4; u++) {
            int idx = u * 256 + tid;
            int r = idx >> 4, un = idx & 15;
            uint32_t soff = (uint32_t)(r * 256) + (uint32_t)((un >> 3) * 128) +
                            (uint32_t)((((un & 7) ^ (r & 7)) & 7) << 4);
            cp_async16(kb + soff, kc + (size_t)r * 128 + un * 8);
            cp_async16(vb + soff, vc + (size_t)r * 128 + un * 8);
        }
        cp_commit();
    };
    load_kv(0, 0);
    load_kv(1, 1);

    float O[8][4];
    #pragma unroll
    for (int j = 0; j < 8; j++)
        #pragma unroll
        for (int t = 0; t < 4; t++) O[j][t] = 0.f;
    float m0 = NEG_INF, m1 = NEG_INF, l0 = 0.f, l1 = 0.f;

    const int lrow = lane & 15;
    const int lsel = lane >> 4;
    const int qg0 = q0 + wid * 16 + (lane >> 2);
    const int qr = wid * 16 + lrow;

    for (int kt = 0; kt < 8; kt++) {
        if (kt == 7) cp_wait<0>(); else cp_wait<1>();
        __syncthreads();
        uint32_t kbase = sb + FA_SK + (kt & 1) * 16384;
        uint32_t vbase = sb + FA_SV + (kt & 1) * 16384;

        float S[8][4];
        #pragma unroll
        for (int j = 0; j < 8; j++)
            #pragma unroll
            for (int t = 0; t < 4; t++) S[j][t] = 0.f;

        #pragma unroll
        for (int c = 0; c < 4; c++) {
            uint32_t qco = (uint32_t)((((2 * c + lsel) ^ (qr & 7)) & 7) << 4);
            uint32_t aqh[4], aql[4];
            ldm_x4(aqh[0], aqh[1], aqh[2], aqh[3], sb + (uint32_t)(qr * 256) + qco);
            ldm_x4(aql[0], aql[1], aql[2], aql[3],
                   sb + (uint32_t)(qr * 256) + 128 + qco);
            #pragma unroll
            for (int kg = 0; kg < 4; kg++) {
                int kr = kg * 16 + lrow;
                uint32_t kco = (uint32_t)((((2 * c + lsel) ^ (kr & 7)) & 7) << 4);
                uint32_t bkh[4], bkl[4];
                ldm_x4(bkh[0], bkh[1], bkh[2], bkh[3],
                       kbase + (uint32_t)(kr * 256) + kco);
                ldm_x4(bkl[0], bkl[1], bkl[2], bkl[3],
                       kbase + (uint32_t)(kr * 256) + 128 + kco);
                #pragma unroll
                for (int sbt = 0; sbt < 2; sbt++) {
                    int j = 2 * kg + sbt;
                    mma_bf16(S[j], aqh, bkh[sbt], bkh[2 + sbt]);
                    mma_bf16(S[j], aqh, bkl[sbt], bkl[2 + sbt]);
                    mma_bf16(S[j], aql, bkh[sbt], bkh[2 + sbt]);
                }
            }
        }

        const int k0 = kt * 64;
        float mloc0 = NEG_INF, mloc1 = NEG_INF;
        #pragma unroll
        for (int j = 0; j < 8; j++) {
            int key = k0 + 8 * j + (lane & 3) * 2;
            float2 bi0 = *(const float2*)(sim + (size_t)qg0 * SEQ + key);
            float2 bi1 = *(const float2*)(sim + (size_t)(qg0 + 8) * SEQ + key);
            S[j][0] = S[j][0] * SC2 + wh * bi0.x;
            S[j][1] = S[j][1] * SC2 + wh * bi0.y;
            S[j][2] = S[j][2] * SC2 + wh * bi1.x;
            S[j][3] = S[j][3] * SC2 + wh * bi1.y;
            mloc0 = fmaxf(mloc0, fmaxf(S[j][0], S[j][1]));
            mloc1 = fmaxf(mloc1, fmaxf(S[j][2], S[j][3]));
        }
        #pragma unroll
        for (int off = 1; off <= 2; off <<= 1) {
            mloc0 = fmaxf(mloc0, __shfl_xor_sync(0xffffffffu, mloc0, off));
            mloc1 = fmaxf(mloc1, __shfl_xor_sync(0xffffffffu, mloc1, off));
        }
        float mn0 = fmaxf(m0, mloc0), mn1 = fmaxf(m1, mloc1);
        float corr0 = exp2f(m0 - mn0), corr1 = exp2f(m1 - mn1);
        m0 = mn0; m1 = mn1;
        float ps0 = 0.f, ps1 = 0.f;
        #pragma unroll
        for (int j = 0; j < 8; j++) {
            S[j][0] = exp2f(S[j][0] - mn0);
            S[j][1] = exp2f(S[j][1] - mn0);
            S[j][2] = exp2f(S[j][2] - mn1);
            S[j][3] = exp2f(S[j][3] - mn1);
            ps0 += S[j][0] + S[j][1];
            ps1 += S[j][2] + S[j][3];
        }
        #pragma unroll
        for (int off = 1; off <= 2; off <<= 1) {
            ps0 += __shfl_xor_sync(0xffffffffu, ps0, off);
            ps1 += __shfl_xor_sync(0xffffffffu, ps1, off);
        }
        l0 = l0 * corr0 + ps0;
        l1 = l1 * corr1 + ps1;
        #pragma unroll
        for (int j = 0; j < 8; j++) {
            O[j][0] *= corr0; O[j][1] *= corr0;
            O[j][2] *= corr1; O[j][3] *= corr1;
        }

        // ---- O += P V: full 3-product (P hi/lo, V hi/lo) ----
        #pragma unroll
        for (int kg = 0; kg < 4; kg++) {
            uint32_t ph[4], pl[4];
            #pragma unroll
            for (int half = 0; half < 2; half++) {
                #pragma unroll
                for (int rw = 0; rw < 2; rw++) {
                    float x = S[2 * kg + half][rw * 2 + 0];
                    float y = S[2 * kg + half][rw * 2 + 1];
                    __nv_bfloat162 h2 = __float22bfloat162_rn(make_float2(x, y));
                    float2 hf = __bfloat1622float2(h2);
                    __nv_bfloat162 l2 = __float22bfloat162_rn(
                        make_float2(x - hf.x, y - hf.y));
                    ph[half * 2 + rw] = *(uint32_t*)&h2;
                    pl[half * 2 + rw] = *(uint32_t*)&l2;
                }
            }
            int kr = kg * 16 + (lane & 7) + (((lane >> 3) & 1) << 3);
            #pragma unroll
            for (int db = 0; db < 4; db++) {
                uint32_t vco =
                    (uint32_t)((((2 * db + (lane >> 4)) ^ (kr & 7)) & 7) << 4);
                uint32_t vh[4], vl[4];
                ldm_x4_t(vh[0], vh[1], vh[2], vh[3],
                         vbase + (uint32_t)(kr * 256) + vco);
                ldm_x4_t(vl[0], vl[1], vl[2], vl[3],
                         vbase + (uint32_t)(kr * 256) + 128 + vco);
                mma_bf16(O[2 * db], ph, vh[0], vh[1]);
                mma_bf16(O[2 * db], ph, vl[0], vl[1]);
                mma_bf16(O[2 * db], pl, vh[0], vh[1]);
                mma_bf16(O[2 * db + 1], ph, vh[2], vh[3]);
                mma_bf16(O[2 * db + 1], ph, vl[2], vl[3]);
                mma_bf16(O[2 * db + 1], pl, vh[2], vh[3]);
            }
        }
        __syncthreads();
        if (kt + 2 < 8) load_kv(kt + 2, kt & 1);
    }

    // ---- staged epilogue: normalize, split hi/lo into smem, coalesce out ---
    __syncthreads();   // K/V stage buffers dead
    float inv0 = 1.f / l0, inv1 = 1.f / l1;
    #pragma unroll
    for (int j = 0; j < 8; j++) {
        int d = 8 * j + (lane & 3) * 2;
        #pragma unroll
        for (int half = 0; half < 2; half++) {
            int rl = wid * 16 + (lane >> 2) + half * 8;
            float x = O[j][half * 2 + 0] * (half ? inv1 : inv0);
            float y = O[j][half * 2 + 1] * (half ? inv1 : inv0);
            __nv_bfloat162 h2 = __float22bfloat162_rn(make_float2(x, y));
            float2 hf = __bfloat1622float2(h2);
            __nv_bfloat162 l2 = __float22bfloat162_rn(
                make_float2(x - hf.x, y - hf.y));
            char* p = sm + rl * FE_ROW + d * 2;
            *(__nv_bfloat162*)p = h2;
            *(__nv_bfloat162*)(p + 128) = l2;
        }
    }
    __syncthreads();
    const size_t rowbase = (size_t)b * 512 + q0;
    #pragma unroll
    for (int it = 0; it < 8; it++) {
        int id = it * 256 + tid;
        int row = id >> 4, ci = id & 15;
        float4 v = *(const float4*)(sm + row * FE_ROW + ci * 16);
        __nv_bfloat16* dst = C2 + (rowbase + row) * K2 + h * 64 +
                             (ci < 8 ? ci * 8 : RELDIM + (ci - 8) * 8);
        *(float4*)dst = v;
    }
}

// ---------------- launch ----------------------------------------------------
extern "C" void kernel_launch(void* const* d_in, const int* in_sizes, int n_in,
                              void* d_out, int out_size) {
    (void)in_sizes; (void)n_in; (void)out_size;
    const float* h_R  = (const float*)d_in[0];
    const float* R    = (const float*)d_in[1];
    const float* W_q  = (const float*)d_in[2];
    const float* W_k  = (const float*)d_in[3];
    const float* W_v  = (const float*)d_in[4];
    const float* W_o  = (const float*)d_in[5];
    const float* wsim = (const float*)d_in[6];
    float* out = (float*)d_out;

    float *Rnp, *Simp;
    __nv_bfloat16 *A2p, *C2p, *Wqkv2p, *Wo2p, *Q2p, *K2p, *V2p;
    cudaGetSymbolAddress((void**)&Rnp,    g_Rn);
    cudaGetSymbolAddress((void**)&Simp,   g_sim);
    cudaGetSymbolAddress((void**)&A2p,    g_A2);
    cudaGetSymbolAddress((void**)&C2p,    g_C2);
    cudaGetSymbolAddress((void**)&Wqkv2p, g_Wqkv2);
    cudaGetSymbolAddress((void**)&Wo2p,   g_Wo2);
    cudaGetSymbolAddress((void**)&Q2p,    g_Q2);
    cudaGetSymbolAddress((void**)&K2p,    g_K2);
    cudaGetSymbolAddress((void**)&V2p,    g_V2);

    const int M = BATCH * SEQ;  // 16384
    const size_t WSZ = (size_t)RELDIM * K2;

    {
        int t4 = M * RELDIM / 4;
        split2<<<(t4 + 511) / 512, 256>>>(h_R, A2p, t4, RELDIM);
        int w4 = RELDIM * RELDIM / 4;
        split2w<<<dim3((w4 + 511) / 512, 4), 256>>>(
            W_q, W_k, W_v, W_o,
            Wqkv2p, Wqkv2p + WSZ, Wqkv2p + 2 * WSZ, Wo2p, w4, RELDIM);
    }

    constexpr int GEMM_SMEM = 3 * GM_STAGE;  // 98304 >= 128*528
    cudaFuncSetAttribute(gemm_mma, cudaFuncAttributeMaxDynamicSharedMemorySize,
                         GEMM_SMEM);
    gemm_mma<<<dim3(24, M / 128), 256, GEMM_SMEM>>>(
        A2p, Wqkv2p, nullptr, Q2p, K2p, V2p, 3 * RELDIM, K2, 1);

    norm_kernel<<<SEQ, 256>>>(R, Rnp);
    gemm_nt64<<<dim3(SEQ / 64, SEQ / 64), 128>>>(Rnp, Rnp, Simp, SEQ, SEQ, REMB);

    cudaFuncSetAttribute(flash_mma, cudaFuncAttributeMaxDynamicSharedMemorySize,
                         FA_SMEM);
    flash_mma<<<dim3(SEQ / 128, BATCH * NH), 256, FA_SMEM>>>(
        Q2p, K2p, V2p, Simp, wsim, C2p);

    gemm_mma<<<dim3(8, M / 128), 256, GEMM_SMEM>>>(
        C2p, Wo2p, out, nullptr, nullptr, nullptr, RELDIM, K2, 0);
}